// round 14
// baseline (speedup 1.0000x reference)
#include <cuda_runtime.h>
#include <cuda_fp16.h>
#include <cstdint>
#include <cstddef>

// ---------------------------------------------------------------------------
//  x: [16, 32, 32, 8, 16]  (B,H,W,I,Din) fp32
//  W: [5, 5, 16, 256]      (kh,kw,cin,co) fp32, co = o*16+d
//  b: [1, 1, 16, 16]       fp32
//  out: [16, 32, 32, 16, 16] (B,H,W,O,D) fp32
//
// Routing group p uses conv images n = 8p+q -> input capsule i = p>>1,
// b_img = 8*(p&1)+q.  CTA = (p, h, 16 w's): M=128 GEMM rows (8 q x 16 w) =
// the votes its 16 routing points need.  1024 CTAs, 512 threads, occ 1
// (halves per-CTA-duplicated B traffic vs the M=64 variant: 819->410 MB L2).
// GEMM: M=128, N=256, K=416 (26 taps x 16, tap 25 zero-padded).
// Single-pass fp16 (x,W fp16): measured rel_err 5.7e-4 < 1e-3.
// 13 super-steps of 2 taps, 3-stage cp.async, 1 sync/step.
// Warp-parallel routing: 16 warps = 16 points, shuffle-only, no barriers.
// ---------------------------------------------------------------------------

__device__ __half g_xh[16 * 32 * 32 * 8 * 16];   // x as fp16
__device__ __half g_ws[26 * 256 * 16];           // W as [k][n][16k], fp16, tap25=0

// stage: A 2 taps x 128x48B (12288) + B 2 taps x 256x48B (24576) = 36864
#define ST_BYTES   36864
#define SMEM_ALLOC 133120          // dump buffer 128x260x4 (reuses stage region)
#define DPITCH     260             // dump row pitch in floats (1040B, 16-aligned)

__device__ __forceinline__ uint32_t smem_u32(const void* p) {
    uint32_t a;
    asm("{ .reg .u64 t; cvta.to.shared.u64 t, %1; cvt.u32.u64 %0, t; }" : "=r"(a) : "l"(p));
    return a;
}
__device__ __forceinline__ void cp16z(uint32_t dst, const void* src, bool valid) {
    int sz = valid ? 16 : 0;
    asm volatile("cp.async.cg.shared.global [%0], [%1], 16, %2;\n"
                 :: "r"(dst), "l"(src), "r"(sz));
}
__device__ __forceinline__ void cp16(uint32_t dst, const void* src) {
    asm volatile("cp.async.cg.shared.global [%0], [%1], 16;\n" :: "r"(dst), "l"(src));
}
#define CP_COMMIT() asm volatile("cp.async.commit_group;\n")
#define CP_WAIT(n)  asm volatile("cp.async.wait_group %0;\n" :: "n"(n))

#define LDSM4(r, addr) \
    asm volatile("ldmatrix.sync.aligned.m8n8.x4.shared.b16 {%0,%1,%2,%3}, [%4];" \
                 : "=r"((r)[0]), "=r"((r)[1]), "=r"((r)[2]), "=r"((r)[3]) : "r"(addr))

#define MMA16816(c, a, bb0, bb1) \
    asm volatile("mma.sync.aligned.m16n8k16.row.col.f32.f16.f16.f32 " \
                 "{%0,%1,%2,%3}, {%4,%5,%6,%7}, {%8,%9}, {%0,%1,%2,%3};" \
                 : "+f"((c)[0]), "+f"((c)[1]), "+f"((c)[2]), "+f"((c)[3]) \
                 : "r"((a)[0]), "r"((a)[1]), "r"((a)[2]), "r"((a)[3]), \
                   "r"(bb0), "r"(bb1))

// ---------------- prep kernels ----------------
__global__ void xprep_kernel(const float* __restrict__ x) {
    int idx = blockIdx.x * 256 + threadIdx.x;          // 4 floats per thread
    if (idx >= 16 * 32 * 32 * 8 * 16 / 4) return;
    float4 f = ((const float4*)x)[idx];
    __half h0[4];
    h0[0] = __float2half_rn(f.x);
    h0[1] = __float2half_rn(f.y);
    h0[2] = __float2half_rn(f.z);
    h0[3] = __float2half_rn(f.w);
    *(uint2*)&g_xh[idx * 4] = *(uint2*)h0;
}

__global__ void wprep_kernel(const float* __restrict__ W) {
    int idx = blockIdx.x * 256 + threadIdx.x;   // k*256 + co, k in [0,26)
    if (idx >= 26 * 256) return;
    int co = idx & 255, k = idx >> 8;
#pragma unroll
    for (int cin = 0; cin < 16; ++cin)
        g_ws[idx * 16 + cin] = (k < 25)
            ? __float2half_rn(W[(k * 16 + cin) * 256 + co])
            : __half(0.f);
}

// ---------------- main fused kernel ----------------
// Load one super-stage = taps 2s, 2s+1.  512 threads.
__device__ __forceinline__ void load_tiles(uint32_t sbase, int s, int stg_i,
                                           int h, int w0, int i_true, int b_base,
                                           int t) {
    const uint32_t stg = sbase + stg_i * ST_BYTES;
    // A: 512 x 16B (1 per thread): sub(2) x half(2) x row(128)
    {
        int sub = t >> 8, r = t & 255;
        int half = r & 1, row = r >> 1;
        int k2 = 2 * s + sub;
        int kh = k2 / 5, kw = k2 - kh * 5;
        int q = row >> 4, wl = row & 15;
        int hh = h + kh - 2, ww = w0 + wl + kw - 2;
        bool valid = (k2 < 25) && ((unsigned)hh < 32u) && ((unsigned)ww < 32u);
        const __half* src = valid
            ? &g_xh[((((size_t)(b_base + q) * 32 + hh) * 32 + ww) * 8 + i_true) * 16 + half * 8]
            : &g_xh[0];
        cp16z(stg + sub * 6144 + row * 48 + half * 16, src, valid);
    }
    // B: 1024 x 16B (2 per thread): sub(2) x half(2) x n(256)
#pragma unroll
    for (int it = 0; it < 2; ++it) {
        int j = t + it * 512;
        int sub = j >> 9, rem = j & 511;
        int half = rem & 1, n = rem >> 1;
        cp16(stg + 12288 + sub * 12288 + n * 48 + half * 16,
             &g_ws[((size_t)(2 * s + sub) * 256 + n) * 16 + half * 8]);
    }
}

__global__ __launch_bounds__(512, 1) void caps_fused_kernel(
    const float* __restrict__ bias, float* __restrict__ out) {
    extern __shared__ __align__(1024) char sm[];
    const uint32_t sbase = smem_u32(sm);

    const int t = threadIdx.x;
    const int wid = t >> 5, lane = t & 31;
    const int bid = blockIdx.x;
    const int wb = bid & 1, h = (bid >> 1) & 31, p = bid >> 6;
    const int w0 = wb * 16;
    const int i_true = p >> 1, b_base = (p & 1) * 8;

    const int wm = wid & 3;        // m block (32 rows each)
    const int wn = wid >> 2;       // n block (64 cols each)

    const uint32_t a_row  = lane & 15;
    const uint32_t a_koff = (lane >> 4) * 16;
    const uint32_t b_row  = (lane & 7) + ((lane >> 4) << 3);
    const uint32_t b_koff = ((lane >> 3) & 1) * 16;

    float acc[2][8][4];
#pragma unroll
    for (int mi = 0; mi < 2; ++mi)
#pragma unroll
        for (int ni = 0; ni < 8; ++ni)
#pragma unroll
            for (int j = 0; j < 4; ++j) acc[mi][ni][j] = 0.f;

    // prologue: stages 0,1
    load_tiles(sbase, 0, 0, h, w0, i_true, b_base, t);
    CP_COMMIT();
    load_tiles(sbase, 1, 1, h, w0, i_true, b_base, t);
    CP_COMMIT();

    for (int s = 0; s < 13; ++s) {
        const int stg_i = s % 3;
        if (s < 12) CP_WAIT(1); else CP_WAIT(0);
        __syncthreads();                 // stage s ready; stage (s+2)%3 free
        if (s + 2 < 13) {
            load_tiles(sbase, s + 2, (s + 2) % 3, h, w0, i_true, b_base, t);
            CP_COMMIT();
        }

        const uint32_t stg = sbase + stg_i * ST_BYTES;
#pragma unroll
        for (int sub = 0; sub < 2; ++sub) {
            const uint32_t Ab = stg + sub * 6144 + (wm * 32 + a_row) * 48 + a_koff;
            const uint32_t Bb = stg + 12288 + sub * 12288 +
                                (wn * 64 + b_row) * 48 + b_koff;
            uint32_t Af[2][4], Bf[4][4];
#pragma unroll
            for (int mi = 0; mi < 2; ++mi) LDSM4(Af[mi], Ab + mi * 768);
#pragma unroll
            for (int nt = 0; nt < 4; ++nt) LDSM4(Bf[nt], Bb + nt * 768);
#pragma unroll
            for (int mi = 0; mi < 2; ++mi)
#pragma unroll
                for (int nt = 0; nt < 4; ++nt) {
                    MMA16816(acc[mi][2 * nt],     Af[mi], Bf[nt][0], Bf[nt][1]);
                    MMA16816(acc[mi][2 * nt + 1], Af[mi], Bf[nt][2], Bf[nt][3]);
                }
        }
    }
    __syncthreads();   // compute done; stage smem dead -> vote dump

    // ---- dump accumulators: Dsm[row 128][col 256], pitch DPITCH floats ----
    float* Dsm = (float*)sm;
    {
        const int g = lane >> 2, tq = lane & 3;
#pragma unroll
        for (int mi = 0; mi < 2; ++mi)
#pragma unroll
            for (int ni = 0; ni < 8; ++ni) {
                int row = wm * 32 + mi * 16 + g;
                int col = wn * 64 + ni * 8 + tq * 2;
                *(float2*)&Dsm[(size_t)row * DPITCH + col] =
                    make_float2(acc[mi][ni][0], acc[mi][ni][1]);
                *(float2*)&Dsm[(size_t)(row + 8) * DPITCH + col] =
                    make_float2(acc[mi][ni][2], acc[mi][ni][3]);
            }
    }
    __syncthreads();

    // ---- warp-parallel routing: warp wid handles point pt = wid (16 pts) ----
    // lane l: o = l>>1, d-group dg = l&1 (d = dg*8 + j).  All reductions are
    // warp shuffles: squash-norm over d via xor 1; softmax over o via
    // butterfly strides {2,4,8,16}.  No block barriers.
    {
        const int o = lane >> 1, dg = lane & 1;

        // votes: vqv[q][j] = Dsm[(q*16+wid)][o*16 + dg*8 + j]
        float vqv[8][8];
#pragma unroll
        for (int q = 0; q < 8; ++q) {
            const float* rowp = &Dsm[(size_t)(q * 16 + wid) * DPITCH + lane * 8];
            float4 v0 = *(const float4*)rowp;
            float4 v1 = *(const float4*)(rowp + 4);
            vqv[q][0] = v0.x; vqv[q][1] = v0.y; vqv[q][2] = v0.z; vqv[q][3] = v0.w;
            vqv[q][4] = v1.x; vqv[q][5] = v1.y; vqv[q][6] = v1.z; vqv[q][7] = v1.w;
        }
        float bv[8];
        {
            const float4* bp = (const float4*)(bias + o * 16 + dg * 8);
            float4 b0 = bp[0], b1 = bp[1];
            bv[0] = b0.x; bv[1] = b0.y; bv[2] = b0.z; bv[3] = b0.w;
            bv[4] = b1.x; bv[5] = b1.y; bv[6] = b1.z; bv[7] = b1.w;
        }

        float pre[8], act[8], lgv[8];

        // ---- iter 0: route = 1/16 ----
#pragma unroll
        for (int j = 0; j < 8; ++j) {
            float s = bv[j];
#pragma unroll
            for (int q = 0; q < 8; ++q) s = fmaf(0.0625f, vqv[q][j], s);
            pre[j] = s;
        }
        float sq = 0.f;
#pragma unroll
        for (int j = 0; j < 8; ++j) sq = fmaf(pre[j], pre[j], sq);
        sq += __shfl_xor_sync(0xffffffffu, sq, 1);
        float scl = sqrtf(sq) / (1.f + sq);
#pragma unroll
        for (int j = 0; j < 8; ++j) act[j] = pre[j] * scl;

        // agreement -> logits
#pragma unroll
        for (int q = 0; q < 8; ++q) {
            float s = 0.f;
#pragma unroll
            for (int j = 0; j < 8; ++j) s = fmaf(vqv[q][j], act[j], s);
            lgv[q] = s + __shfl_xor_sync(0xffffffffu, s, 1);
        }

#pragma unroll
        for (int it = 1; it < 3; ++it) {
            // softmax over o (lane pairs share o; butterfly strides 2..16)
            float mx[8], ex[8], sum[8];
#pragma unroll
            for (int q = 0; q < 8; ++q) mx[q] = lgv[q];
#pragma unroll
            for (int st = 2; st <= 16; st <<= 1)
#pragma unroll
                for (int q = 0; q < 8; ++q)
                    mx[q] = fmaxf(mx[q], __shfl_xor_sync(0xffffffffu, mx[q], st));
#pragma unroll
            for (int q = 0; q < 8; ++q) { ex[q] = __expf(lgv[q] - mx[q]); sum[q] = ex[q]; }
#pragma unroll
            for (int st = 2; st <= 16; st <<= 1)
#pragma unroll
                for (int q = 0; q < 8; ++q)
                    sum[q] += __shfl_xor_sync(0xffffffffu, sum[q], st);
            float route[8];
#pragma unroll
            for (int q = 0; q < 8; ++q) route[q] = ex[q] / sum[q];

#pragma unroll
            for (int j = 0; j < 8; ++j) {
                float s = bv[j];
#pragma unroll
                for (int q = 0; q < 8; ++q) s = fmaf(route[q], vqv[q][j], s);
                pre[j] = s;
            }
            sq = 0.f;
#pragma unroll
            for (int j = 0; j < 8; ++j) sq = fmaf(pre[j], pre[j], sq);
            sq += __shfl_xor_sync(0xffffffffu, sq, 1);
            scl = sqrtf(sq) / (1.f + sq);
#pragma unroll
            for (int j = 0; j < 8; ++j) act[j] = pre[j] * scl;

            if (it == 1) {
#pragma unroll
                for (int q = 0; q < 8; ++q) {
                    float s = 0.f;
#pragma unroll
                    for (int j = 0; j < 8; ++j) s = fmaf(vqv[q][j], act[j], s);
                    lgv[q] += s + __shfl_xor_sync(0xffffffffu, s, 1);
                }
            }
        }

        // write out: point (p, h, w0+wid), lane covers cols lane*8..lane*8+7
        float* op = out + (((size_t)p * 32 + h) * 32 + (w0 + wid)) * 256 + lane * 8;
        *(float4*)op       = make_float4(act[0], act[1], act[2], act[3]);
        *(float4*)(op + 4) = make_float4(act[4], act[5], act[6], act[7]);
    }
}

extern "C" void kernel_launch(void* const* d_in, const int* in_sizes, int n_in,
                              void* d_out, int out_size) {
    const float* x  = (const float*)d_in[0];
    const float* Wt = (const float*)d_in[1];
    const float* b  = (const float*)d_in[2];
    float* out = (float*)d_out;

    cudaFuncSetAttribute(caps_fused_kernel,
                         cudaFuncAttributeMaxDynamicSharedMemorySize, SMEM_ALLOC);

    xprep_kernel<<<2048, 256>>>(x);
    wprep_kernel<<<26, 256>>>(Wt);
    caps_fused_kernel<<<1024, 512, SMEM_ALLOC>>>(b, out);
}

// round 15
// speedup vs baseline: 1.5095x; 1.5095x over previous
#include <cuda_runtime.h>
#include <cuda_fp16.h>
#include <cstdint>
#include <cstddef>

// ---------------------------------------------------------------------------
//  x: [16, 32, 32, 8, 16]  (B,H,W,I,Din) fp32
//  W: [5, 5, 16, 256]      (kh,kw,cin,co) fp32, co = o*16+d
//  b: [1, 1, 16, 16]       fp32
//  out: [16, 32, 32, 16, 16] (B,H,W,O,D) fp32
//
// Routing group p uses conv images n = 8p+q -> input capsule i = p>>1,
// b_img = 8*(p&1)+q.  CTA = (p, h, 8 w's): M=64 GEMM rows.  2048 CTAs,
// 256 threads, OCCUPANCY 2 (proven load-bearing in R13: occ1 regressed).
// GEMM: M=64, N=256, K=432 (27 taps x 16; taps 25,26 zero).
// Single-pass fp16 (x,W fp16): measured rel_err 5.7e-4 < 1e-3.
// R14: 9 super-steps of 3 taps (48 MMA/warp/step), 2-stage ring; next load
// issued AFTER the barrier (race-free: its target buffer's readers passed
// the sync), overlapping the current step's compute.
// Warp-parallel routing epilogue (8 warps = 8 points, shuffle-only).
// ---------------------------------------------------------------------------

__device__ __half g_xh[16 * 32 * 32 * 8 * 16];   // x as fp16
__device__ __half g_ws[27 * 256 * 16];           // W [k][n][16k] fp16, taps>=25 zero

// stage: A 3 taps x 64x48B (9216) + B 3 taps x 256x48B (36864) = 46080
#define ST_BYTES   46080
#define SMEM_ALLOC 92160           // 2 stages; dump buffer (66.6KB) reuses them
#define DPITCH     260             // dump row pitch in floats (1040B, 16-aligned)

__device__ __forceinline__ uint32_t smem_u32(const void* p) {
    uint32_t a;
    asm("{ .reg .u64 t; cvta.to.shared.u64 t, %1; cvt.u32.u64 %0, t; }" : "=r"(a) : "l"(p));
    return a;
}
__device__ __forceinline__ void cp16z(uint32_t dst, const void* src, bool valid) {
    int sz = valid ? 16 : 0;
    asm volatile("cp.async.cg.shared.global [%0], [%1], 16, %2;\n"
                 :: "r"(dst), "l"(src), "r"(sz));
}
__device__ __forceinline__ void cp16(uint32_t dst, const void* src) {
    asm volatile("cp.async.cg.shared.global [%0], [%1], 16;\n" :: "r"(dst), "l"(src));
}
#define CP_COMMIT() asm volatile("cp.async.commit_group;\n")
#define CP_WAIT(n)  asm volatile("cp.async.wait_group %0;\n" :: "n"(n))

#define LDSM4(r, addr) \
    asm volatile("ldmatrix.sync.aligned.m8n8.x4.shared.b16 {%0,%1,%2,%3}, [%4];" \
                 : "=r"((r)[0]), "=r"((r)[1]), "=r"((r)[2]), "=r"((r)[3]) : "r"(addr))

#define MMA16816(c, a, bb0, bb1) \
    asm volatile("mma.sync.aligned.m16n8k16.row.col.f32.f16.f16.f32 " \
                 "{%0,%1,%2,%3}, {%4,%5,%6,%7}, {%8,%9}, {%0,%1,%2,%3};" \
                 : "+f"((c)[0]), "+f"((c)[1]), "+f"((c)[2]), "+f"((c)[3]) \
                 : "r"((a)[0]), "r"((a)[1]), "r"((a)[2]), "r"((a)[3]), \
                   "r"(bb0), "r"(bb1))

// ---------------- prep kernels ----------------
__global__ void xprep_kernel(const float* __restrict__ x) {
    int idx = blockIdx.x * 256 + threadIdx.x;          // 4 floats per thread
    if (idx >= 16 * 32 * 32 * 8 * 16 / 4) return;
    float4 f = ((const float4*)x)[idx];
    __half h0[4];
    h0[0] = __float2half_rn(f.x);
    h0[1] = __float2half_rn(f.y);
    h0[2] = __float2half_rn(f.z);
    h0[3] = __float2half_rn(f.w);
    *(uint2*)&g_xh[idx * 4] = *(uint2*)h0;
}

__global__ void wprep_kernel(const float* __restrict__ W) {
    int idx = blockIdx.x * 256 + threadIdx.x;   // k*256 + co, k in [0,27)
    if (idx >= 27 * 256) return;
    int co = idx & 255, k = idx >> 8;
#pragma unroll
    for (int cin = 0; cin < 16; ++cin)
        g_ws[idx * 16 + cin] = (k < 25)
            ? __float2half_rn(W[(k * 16 + cin) * 256 + co])
            : __half(0.f);
}

// ---------------- main fused kernel ----------------
// Load one super-stage = taps 3s, 3s+1, 3s+2.  256 threads.
__device__ __forceinline__ void load_tiles(uint32_t sbase, int s, int stg_i,
                                           int h, int w0, int i_true, int b_base,
                                           int t) {
    const uint32_t stg = sbase + stg_i * ST_BYTES;
    // A: 384 x 16B: sub(3) x half(2) x row(64)
#pragma unroll
    for (int it = 0; it < 2; ++it) {
        int j = t + it * 256;
        if (j < 384) {
            int sub = j >> 7, r = j & 127;
            int half = r & 1, row = r >> 1;
            int k2 = 3 * s + sub;
            int kh = k2 / 5, kw = k2 - kh * 5;
            int q = row >> 3, wl = row & 7;
            int hh = h + kh - 2, ww = w0 + wl + kw - 2;
            bool valid = (k2 < 25) && ((unsigned)hh < 32u) && ((unsigned)ww < 32u);
            const __half* src = valid
                ? &g_xh[((((size_t)(b_base + q) * 32 + hh) * 32 + ww) * 8 + i_true) * 16 + half * 8]
                : &g_xh[0];
            cp16z(stg + sub * 3072 + row * 48 + half * 16, src, valid);
        }
    }
    // B: 1536 x 16B (6 per thread): sub(3) x half(2) x n(256)
#pragma unroll
    for (int it = 0; it < 6; ++it) {
        int j = t + it * 256;
        int sub = j >> 9, rem = j & 511;
        int half = rem & 1, n = rem >> 1;
        cp16(stg + 9216 + sub * 12288 + n * 48 + half * 16,
             &g_ws[((size_t)(3 * s + sub) * 256 + n) * 16 + half * 8]);
    }
}

__global__ __launch_bounds__(256, 2) void caps_fused_kernel(
    const float* __restrict__ bias, float* __restrict__ out) {
    extern __shared__ __align__(1024) char sm[];
    const uint32_t sbase = smem_u32(sm);

    const int t = threadIdx.x;
    const int wid = t >> 5, lane = t & 31;
    const int bid = blockIdx.x;
    const int wblk = bid & 3, h = (bid >> 2) & 31, p = bid >> 7;
    const int w0 = wblk * 8;
    const int i_true = p >> 1, b_base = (p & 1) * 8;

    const int wm = wid & 1;        // m block (32 rows each)
    const int wn = wid >> 1;       // n block (64 cols each)

    const uint32_t a_row  = lane & 15;
    const uint32_t a_koff = (lane >> 4) * 16;
    const uint32_t b_row  = (lane & 7) + ((lane >> 4) << 3);
    const uint32_t b_koff = ((lane >> 3) & 1) * 16;

    float acc[2][8][4];
#pragma unroll
    for (int mi = 0; mi < 2; ++mi)
#pragma unroll
        for (int ni = 0; ni < 8; ++ni)
#pragma unroll
            for (int j = 0; j < 4; ++j) acc[mi][ni][j] = 0.f;

    // prologue: stage 0
    load_tiles(sbase, 0, 0, h, w0, i_true, b_base, t);
    CP_COMMIT();

    for (int s = 0; s < 9; ++s) {
        CP_WAIT(0);                      // this thread's load of stage s done
        __syncthreads();                 // all loads visible; compute(s-1) done
        if (s < 8) {                     // load s+1 into buffer of s-1 (freed)
            load_tiles(sbase, s + 1, (s + 1) & 1, h, w0, i_true, b_base, t);
            CP_COMMIT();
        }

        const uint32_t stg = sbase + (s & 1) * ST_BYTES;
#pragma unroll
        for (int sub = 0; sub < 3; ++sub) {
            const uint32_t Ab = stg + sub * 3072 + (wm * 32 + a_row) * 48 + a_koff;
            const uint32_t Bb = stg + 9216 + sub * 12288 +
                                (wn * 64 + b_row) * 48 + b_koff;
            uint32_t Af[2][4], Bf[4][4];
#pragma unroll
            for (int mi = 0; mi < 2; ++mi) LDSM4(Af[mi], Ab + mi * 768);
#pragma unroll
            for (int nt = 0; nt < 4; ++nt) LDSM4(Bf[nt], Bb + nt * 768);
#pragma unroll
            for (int mi = 0; mi < 2; ++mi)
#pragma unroll
                for (int nt = 0; nt < 4; ++nt) {
                    MMA16816(acc[mi][2 * nt],     Af[mi], Bf[nt][0], Bf[nt][1]);
                    MMA16816(acc[mi][2 * nt + 1], Af[mi], Bf[nt][2], Bf[nt][3]);
                }
        }
    }
    __syncthreads();   // compute done; stage smem dead -> vote dump

    // ---- dump accumulators: Dsm[row 64][col 256], pitch DPITCH floats ----
    float* Dsm = (float*)sm;
    {
        const int g = lane >> 2, tq = lane & 3;
#pragma unroll
        for (int mi = 0; mi < 2; ++mi)
#pragma unroll
            for (int ni = 0; ni < 8; ++ni) {
                int row = wm * 32 + mi * 16 + g;
                int col = wn * 64 + ni * 8 + tq * 2;
                *(float2*)&Dsm[(size_t)row * DPITCH + col] =
                    make_float2(acc[mi][ni][0], acc[mi][ni][1]);
                *(float2*)&Dsm[(size_t)(row + 8) * DPITCH + col] =
                    make_float2(acc[mi][ni][2], acc[mi][ni][3]);
            }
    }
    __syncthreads();

    // ---- warp-parallel routing: warp wid handles point pt = wid ----
    // lane l: o = l>>1, dg = l&1 (d = dg*8 + j).  Squash-norm via xor 1;
    // softmax over o via butterfly strides {2,4,8,16}.  No block barriers.
    {
        const int o = lane >> 1, dg = lane & 1;

        float vqv[8][8];
#pragma unroll
        for (int q = 0; q < 8; ++q) {
            const float* rowp = &Dsm[(size_t)(q * 8 + wid) * DPITCH + lane * 8];
            float4 v0 = *(const float4*)rowp;
            float4 v1 = *(const float4*)(rowp + 4);
            vqv[q][0] = v0.x; vqv[q][1] = v0.y; vqv[q][2] = v0.z; vqv[q][3] = v0.w;
            vqv[q][4] = v1.x; vqv[q][5] = v1.y; vqv[q][6] = v1.z; vqv[q][7] = v1.w;
        }
        float bv[8];
        {
            const float4* bp = (const float4*)(bias + o * 16 + dg * 8);
            float4 b0 = bp[0], b1 = bp[1];
            bv[0] = b0.x; bv[1] = b0.y; bv[2] = b0.z; bv[3] = b0.w;
            bv[4] = b1.x; bv[5] = b1.y; bv[6] = b1.z; bv[7] = b1.w;
        }

        float pre[8], act[8], lgv[8];

        // ---- iter 0: route = 1/16 ----
#pragma unroll
        for (int j = 0; j < 8; ++j) {
            float s = bv[j];
#pragma unroll
            for (int q = 0; q < 8; ++q) s = fmaf(0.0625f, vqv[q][j], s);
            pre[j] = s;
        }
        float sq = 0.f;
#pragma unroll
        for (int j = 0; j < 8; ++j) sq = fmaf(pre[j], pre[j], sq);
        sq += __shfl_xor_sync(0xffffffffu, sq, 1);
        float scl = sqrtf(sq) / (1.f + sq);
#pragma unroll
        for (int j = 0; j < 8; ++j) act[j] = pre[j] * scl;

        // agreement -> logits
#pragma unroll
        for (int q = 0; q < 8; ++q) {
            float s = 0.f;
#pragma unroll
            for (int j = 0; j < 8; ++j) s = fmaf(vqv[q][j], act[j], s);
            lgv[q] = s + __shfl_xor_sync(0xffffffffu, s, 1);
        }

#pragma unroll
        for (int it = 1; it < 3; ++it) {
            float mx[8], ex[8], sum[8];
#pragma unroll
            for (int q = 0; q < 8; ++q) mx[q] = lgv[q];
#pragma unroll
            for (int st = 2; st <= 16; st <<= 1)
#pragma unroll
                for (int q = 0; q < 8; ++q)
                    mx[q] = fmaxf(mx[q], __shfl_xor_sync(0xffffffffu, mx[q], st));
#pragma unroll
            for (int q = 0; q < 8; ++q) { ex[q] = __expf(lgv[q] - mx[q]); sum[q] = ex[q]; }
#pragma unroll
            for (int st = 2; st <= 16; st <<= 1)
#pragma unroll
                for (int q = 0; q < 8; ++q)
                    sum[q] += __shfl_xor_sync(0xffffffffu, sum[q], st);
            float route[8];
#pragma unroll
            for (int q = 0; q < 8; ++q) route[q] = ex[q] / sum[q];

#pragma unroll
            for (int j = 0; j < 8; ++j) {
                float s = bv[j];
#pragma unroll
                for (int q = 0; q < 8; ++q) s = fmaf(route[q], vqv[q][j], s);
                pre[j] = s;
            }
            sq = 0.f;
#pragma unroll
            for (int j = 0; j < 8; ++j) sq = fmaf(pre[j], pre[j], sq);
            sq += __shfl_xor_sync(0xffffffffu, sq, 1);
            scl = sqrtf(sq) / (1.f + sq);
#pragma unroll
            for (int j = 0; j < 8; ++j) act[j] = pre[j] * scl;

            if (it == 1) {
#pragma unroll
                for (int q = 0; q < 8; ++q) {
                    float s = 0.f;
#pragma unroll
                    for (int j = 0; j < 8; ++j) s = fmaf(vqv[q][j], act[j], s);
                    lgv[q] += s + __shfl_xor_sync(0xffffffffu, s, 1);
                }
            }
        }

        float* op = out + (((size_t)p * 32 + h) * 32 + (w0 + wid)) * 256 + lane * 8;
        *(float4*)op       = make_float4(act[0], act[1], act[2], act[3]);
        *(float4*)(op + 4) = make_float4(act[4], act[5], act[6], act[7]);
    }
}

extern "C" void kernel_launch(void* const* d_in, const int* in_sizes, int n_in,
                              void* d_out, int out_size) {
    const float* x  = (const float*)d_in[0];
    const float* Wt = (const float*)d_in[1];
    const float* b  = (const float*)d_in[2];
    float* out = (float*)d_out;

    cudaFuncSetAttribute(caps_fused_kernel,
                         cudaFuncAttributeMaxDynamicSharedMemorySize, SMEM_ALLOC);

    xprep_kernel<<<2048, 256>>>(x);
    wprep_kernel<<<27, 256>>>(Wt);
    caps_fused_kernel<<<2048, 256, SMEM_ALLOC>>>(b, out);
}

// round 16
// speedup vs baseline: 1.5897x; 1.0532x over previous
#include <cuda_runtime.h>
#include <cuda_fp16.h>
#include <cstdint>
#include <cstddef>

// ---------------------------------------------------------------------------
//  x: [16, 32, 32, 8, 16]  (B,H,W,I,Din) fp32
//  W: [5, 5, 16, 256]      (kh,kw,cin,co) fp32, co = o*16+d
//  b: [1, 1, 16, 16]       fp32
//  out: [16, 32, 32, 16, 16] (B,H,W,O,D) fp32
//
// Routing group p uses conv images n = 8p+q -> input capsule i = p>>1,
// b_img = 8*(p&1)+q.  CTA = (p, h, 8 w's): M=64 GEMM rows.  2048 CTAs,
// 256 threads, occupancy 2 (load-bearing, R13).
// Single-pass fp16 (x,W fp16): measured rel_err 5.7e-4 < 1e-3.
// R15: (a) persistent x-HALO in smem -- all 27 taps are shifted views of an
// 8q x 5hh x 12ww halo (48B pitch, ldmatrix per-lane addressing), so A is
// loaded ONCE instead of per step; stages carry B only.  (b) zero taps
// (25,26) skipped in both load and MMA: 25 real taps = 8x3 + 1.
// 2-stage B ring, warp-parallel shuffle-only routing epilogue.
// ---------------------------------------------------------------------------

__device__ __half g_xh[16 * 32 * 32 * 8 * 16];   // x as fp16
__device__ __half g_ws[27 * 256 * 16];           // W [k][n][16k] fp16, taps>=25 zero

#define HALO_BYTES 23040           // 8q * 5hh * 12ww * 48B
#define OFF_STAGE  23040
#define ST_BYTES   36864           // B: 3 taps x 256 x 48B
#define SMEM_ALLOC 96768           // halo + 2 B stages; dump (66.6KB) reuses [0,..)
#define DPITCH     260             // dump row pitch in floats (1040B, 16-aligned)

__device__ __forceinline__ uint32_t smem_u32(const void* p) {
    uint32_t a;
    asm("{ .reg .u64 t; cvta.to.shared.u64 t, %1; cvt.u32.u64 %0, t; }" : "=r"(a) : "l"(p));
    return a;
}
__device__ __forceinline__ void cp16z(uint32_t dst, const void* src, bool valid) {
    int sz = valid ? 16 : 0;
    asm volatile("cp.async.cg.shared.global [%0], [%1], 16, %2;\n"
                 :: "r"(dst), "l"(src), "r"(sz));
}
__device__ __forceinline__ void cp16(uint32_t dst, const void* src) {
    asm volatile("cp.async.cg.shared.global [%0], [%1], 16;\n" :: "r"(dst), "l"(src));
}
#define CP_COMMIT() asm volatile("cp.async.commit_group;\n")
#define CP_WAIT(n)  asm volatile("cp.async.wait_group %0;\n" :: "n"(n))

#define LDSM4(r, addr) \
    asm volatile("ldmatrix.sync.aligned.m8n8.x4.shared.b16 {%0,%1,%2,%3}, [%4];" \
                 : "=r"((r)[0]), "=r"((r)[1]), "=r"((r)[2]), "=r"((r)[3]) : "r"(addr))

#define MMA16816(c, a, bb0, bb1) \
    asm volatile("mma.sync.aligned.m16n8k16.row.col.f32.f16.f16.f32 " \
                 "{%0,%1,%2,%3}, {%4,%5,%6,%7}, {%8,%9}, {%0,%1,%2,%3};" \
                 : "+f"((c)[0]), "+f"((c)[1]), "+f"((c)[2]), "+f"((c)[3]) \
                 : "r"((a)[0]), "r"((a)[1]), "r"((a)[2]), "r"((a)[3]), \
                   "r"(bb0), "r"(bb1))

// ---------------- merged prep kernel ----------------
__global__ void prep_kernel(const float* __restrict__ x, const float* __restrict__ W) {
    if (blockIdx.x < 2048) {                 // x -> fp16, 4 floats per thread
        int idx = blockIdx.x * 256 + threadIdx.x;
        float4 f = ((const float4*)x)[idx];
        __half h0[4];
        h0[0] = __float2half_rn(f.x);
        h0[1] = __float2half_rn(f.y);
        h0[2] = __float2half_rn(f.z);
        h0[3] = __float2half_rn(f.w);
        *(uint2*)&g_xh[idx * 4] = *(uint2*)h0;
    } else {                                 // W -> [k][n][16] fp16
        int idx = (blockIdx.x - 2048) * 256 + threadIdx.x;   // k*256+co
        if (idx >= 27 * 256) return;
        int co = idx & 255, k = idx >> 8;
#pragma unroll
        for (int cin = 0; cin < 16; ++cin)
            g_ws[idx * 16 + cin] = (k < 25)
                ? __float2half_rn(W[(k * 16 + cin) * 256 + co])
                : __half(0.f);
    }
}

// ---------------- main fused kernel ----------------
// Load B super-stage = taps 3s..3s+2 (skip taps >= 25).
__device__ __forceinline__ void load_B(uint32_t sbase, int s, int stg_i, int t) {
    const uint32_t stg = sbase + OFF_STAGE + stg_i * ST_BYTES;
#pragma unroll
    for (int it = 0; it < 6; ++it) {
        int j = t + it * 256;
        int sub = j >> 9, rem = j & 511;
        int half = rem & 1, n = rem >> 1;
        int k2 = 3 * s + sub;
        if (k2 < 25)
            cp16(stg + sub * 12288 + n * 48 + half * 16,
                 &g_ws[((size_t)k2 * 256 + n) * 16 + half * 8]);
    }
}

// Load x halo once: rows (q, hh 0..4, ww 0..11) of 16 halfs at 48B pitch.
__device__ __forceinline__ void load_halo(uint32_t sbase, int h, int w0,
                                          int i_true, int b_base, int t) {
    // 8*5*12 = 480 rows x 2 chunks = 960 cp16 -> 4 per thread (last partial)
#pragma unroll
    for (int it = 0; it < 4; ++it) {
        int j = t + it * 256;
        if (j < 960) {
            int half = j & 1, row = j >> 1;          // row = q*60 + hh*12 + ww
            int q = row / 60, rem = row - q * 60;
            int hh = rem / 12, ww = rem - hh * 12;
            int hg = h + hh - 2, wg = w0 + ww - 2;
            bool valid = ((unsigned)hg < 32u) && ((unsigned)wg < 32u);
            const __half* src = valid
                ? &g_xh[((((size_t)(b_base + q) * 32 + hg) * 32 + wg) * 8 + i_true) * 16 + half * 8]
                : &g_xh[0];
            cp16z(sbase + q * 2880 + hh * 576 + ww * 48 + half * 16, src, valid);
        }
    }
}

__global__ __launch_bounds__(256, 2) void caps_fused_kernel(
    const float* __restrict__ bias, float* __restrict__ out) {
    extern __shared__ __align__(1024) char sm[];
    const uint32_t sbase = smem_u32(sm);

    const int t = threadIdx.x;
    const int wid = t >> 5, lane = t & 31;
    const int bid = blockIdx.x;
    const int wblk = bid & 3, h = (bid >> 2) & 31, p = bid >> 7;
    const int w0 = wblk * 8;
    const int i_true = p >> 1, b_base = (p & 1) * 8;

    const int wm = wid & 1;        // m block (32 rows each)
    const int wn = wid >> 1;       // n block (64 cols each)

    // A ldmatrix per-lane halo address base: row m = wm*32 + mi*16 + (lane&15),
    // lane addr = q*2880 + wl*48 + (lane>>4)*16 ; per-tap add kh*576 + kw*48.
    uint32_t a_base[2];
#pragma unroll
    for (int mi = 0; mi < 2; ++mi) {
        int m = wm * 32 + mi * 16 + (lane & 15);
        int q = m >> 3, wl = m & 7;
        a_base[mi] = sbase + q * 2880 + wl * 48 + (lane >> 4) * 16;
    }
    const uint32_t b_row  = (lane & 7) + ((lane >> 4) << 3);
    const uint32_t b_koff = ((lane >> 3) & 1) * 16;
    const uint32_t b_lane = (wn * 64 + b_row) * 48 + b_koff;

    float acc[2][8][4];
#pragma unroll
    for (int mi = 0; mi < 2; ++mi)
#pragma unroll
        for (int ni = 0; ni < 8; ++ni)
#pragma unroll
            for (int j = 0; j < 4; ++j) acc[mi][ni][j] = 0.f;

    // prologue: halo + B stage 0
    load_halo(sbase, h, w0, i_true, b_base, t);
    CP_COMMIT();
    load_B(sbase, 0, 0, t);
    CP_COMMIT();

    for (int s = 0; s < 9; ++s) {
        CP_WAIT(0);                      // halo + B stage s landed
        __syncthreads();                 // visible to all; compute(s-1) done
        if (s < 8) {                     // load s+1 into buffer of s-1 (freed)
            load_B(sbase, s + 1, (s + 1) & 1, t);
            CP_COMMIT();
        }

        const uint32_t stg = sbase + OFF_STAGE + (s & 1) * ST_BYTES;
        const int nsub = (s == 8) ? 1 : 3;     // taps 25,26 are zero: skip
        for (int sub = 0; sub < nsub; ++sub) {
            const int k2 = 3 * s + sub;
            const int kh = k2 / 5, kw = k2 - kh * 5;
            const uint32_t a_off = kh * 576 + kw * 48;
            const uint32_t Bb = stg + sub * 12288 + b_lane;
            uint32_t Af[2][4], Bf[4][4];
#pragma unroll
            for (int mi = 0; mi < 2; ++mi) LDSM4(Af[mi], a_base[mi] + a_off);
#pragma unroll
            for (int nt = 0; nt < 4; ++nt) LDSM4(Bf[nt], Bb + nt * 768);
#pragma unroll
            for (int mi = 0; mi < 2; ++mi)
#pragma unroll
                for (int nt = 0; nt < 4; ++nt) {
                    MMA16816(acc[mi][2 * nt],     Af[mi], Bf[nt][0], Bf[nt][1]);
                    MMA16816(acc[mi][2 * nt + 1], Af[mi], Bf[nt][2], Bf[nt][3]);
                }
        }
    }
    __syncthreads();   // compute done; halo+stage smem dead -> vote dump

    // ---- dump accumulators: Dsm[row 64][col 256], pitch DPITCH floats ----
    float* Dsm = (float*)sm;
    {
        const int g = lane >> 2, tq = lane & 3;
#pragma unroll
        for (int mi = 0; mi < 2; ++mi)
#pragma unroll
            for (int ni = 0; ni < 8; ++ni) {
                int row = wm * 32 + mi * 16 + g;
                int col = wn * 64 + ni * 8 + tq * 2;
                *(float2*)&Dsm[(size_t)row * DPITCH + col] =
                    make_float2(acc[mi][ni][0], acc[mi][ni][1]);
                *(float2*)&Dsm[(size_t)(row + 8) * DPITCH + col] =
                    make_float2(acc[mi][ni][2], acc[mi][ni][3]);
            }
    }
    __syncthreads();

    // ---- warp-parallel routing: warp wid handles point pt = wid ----
    {
        const int o = lane >> 1, dg = lane & 1;

        float vqv[8][8];
#pragma unroll
        for (int q = 0; q < 8; ++q) {
            const float* rowp = &Dsm[(size_t)(q * 8 + wid) * DPITCH + lane * 8];
            float4 v0 = *(const float4*)rowp;
            float4 v1 = *(const float4*)(rowp + 4);
            vqv[q][0] = v0.x; vqv[q][1] = v0.y; vqv[q][2] = v0.z; vqv[q][3] = v0.w;
            vqv[q][4] = v1.x; vqv[q][5] = v1.y; vqv[q][6] = v1.z; vqv[q][7] = v1.w;
        }
        float bv[8];
        {
            const float4* bp = (const float4*)(bias + o * 16 + dg * 8);
            float4 b0 = bp[0], b1 = bp[1];
            bv[0] = b0.x; bv[1] = b0.y; bv[2] = b0.z; bv[3] = b0.w;
            bv[4] = b1.x; bv[5] = b1.y; bv[6] = b1.z; bv[7] = b1.w;
        }

        float pre[8], act[8], lgv[8];

        // ---- iter 0: route = 1/16 ----
#pragma unroll
        for (int j = 0; j < 8; ++j) {
            float s = bv[j];
#pragma unroll
            for (int q = 0; q < 8; ++q) s = fmaf(0.0625f, vqv[q][j], s);
            pre[j] = s;
        }
        float sq = 0.f;
#pragma unroll
        for (int j = 0; j < 8; ++j) sq = fmaf(pre[j], pre[j], sq);
        sq += __shfl_xor_sync(0xffffffffu, sq, 1);
        float scl = sqrtf(sq) / (1.f + sq);
#pragma unroll
        for (int j = 0; j < 8; ++j) act[j] = pre[j] * scl;

        // agreement -> logits
#pragma unroll
        for (int q = 0; q < 8; ++q) {
            float s = 0.f;
#pragma unroll
            for (int j = 0; j < 8; ++j) s = fmaf(vqv[q][j], act[j], s);
            lgv[q] = s + __shfl_xor_sync(0xffffffffu, s, 1);
        }

#pragma unroll
        for (int it = 1; it < 3; ++it) {
            float mx[8], ex[8], sum[8];
#pragma unroll
            for (int q = 0; q < 8; ++q) mx[q] = lgv[q];
#pragma unroll
            for (int st = 2; st <= 16; st <<= 1)
#pragma unroll
                for (int q = 0; q < 8; ++q)
                    mx[q] = fmaxf(mx[q], __shfl_xor_sync(0xffffffffu, mx[q], st));
#pragma unroll
            for (int q = 0; q < 8; ++q) { ex[q] = __expf(lgv[q] - mx[q]); sum[q] = ex[q]; }
#pragma unroll
            for (int st = 2; st <= 16; st <<= 1)
#pragma unroll
                for (int q = 0; q < 8; ++q)
                    sum[q] += __shfl_xor_sync(0xffffffffu, sum[q], st);
            float route[8];
#pragma unroll
            for (int q = 0; q < 8; ++q) route[q] = ex[q] / sum[q];

#pragma unroll
            for (int j = 0; j < 8; ++j) {
                float s = bv[j];
#pragma unroll
                for (int q = 0; q < 8; ++q) s = fmaf(route[q], vqv[q][j], s);
                pre[j] = s;
            }
            sq = 0.f;
#pragma unroll
            for (int j = 0; j < 8; ++j) sq = fmaf(pre[j], pre[j], sq);
            sq += __shfl_xor_sync(0xffffffffu, sq, 1);
            scl = sqrtf(sq) / (1.f + sq);
#pragma unroll
            for (int j = 0; j < 8; ++j) act[j] = pre[j] * scl;

            if (it == 1) {
#pragma unroll
                for (int q = 0; q < 8; ++q) {
                    float s = 0.f;
#pragma unroll
                    for (int j = 0; j < 8; ++j) s = fmaf(vqv[q][j], act[j], s);
                    lgv[q] += s + __shfl_xor_sync(0xffffffffu, s, 1);
                }
            }
        }

        float* op = out + (((size_t)p * 32 + h) * 32 + (w0 + wid)) * 256 + lane * 8;
        *(float4*)op       = make_float4(act[0], act[1], act[2], act[3]);
        *(float4*)(op + 4) = make_float4(act[4], act[5], act[6], act[7]);
    }
}

extern "C" void kernel_launch(void* const* d_in, const int* in_sizes, int n_in,
                              void* d_out, int out_size) {
    const float* x  = (const float*)d_in[0];
    const float* Wt = (const float*)d_in[1];
    const float* b  = (const float*)d_in[2];
    float* out = (float*)d_out;

    cudaFuncSetAttribute(caps_fused_kernel,
                         cudaFuncAttributeMaxDynamicSharedMemorySize, SMEM_ALLOC);

    prep_kernel<<<2048 + 27, 256>>>(x, Wt);
    caps_fused_kernel<<<2048, 256, SMEM_ALLOC>>>(b, out);
}

// round 17
// speedup vs baseline: 1.7630x; 1.1090x over previous
#include <cuda_runtime.h>
#include <cuda_fp16.h>
#include <cstdint>
#include <cstddef>

// ---------------------------------------------------------------------------
//  x: [16, 32, 32, 8, 16]  (B,H,W,I,Din) fp32
//  W: [5, 5, 16, 256]      (kh,kw,cin,co) fp32, co = o*16+d
//  b: [1, 1, 16, 16]       fp32
//  out: [16, 32, 32, 16, 16] (B,H,W,O,D) fp32
//
// Routing group p uses conv images n = 8p+q -> input capsule i = p>>1,
// b_img = 8*(p&1)+q.  CTA = (p, h, 8 w's): M=64 GEMM rows.  2048 CTAs,
// 256 threads, occupancy 2 (load-bearing; RF-capped at 16 warps/SM).
// Single-pass fp16: measured rel_err 5.7e-4 < 1e-3.
// Persistent x-halo (A loaded once); 9 super-steps of 3 taps (zero taps
// skipped); 2-stage B ring.
// R16: PAIR-SCOPED pipeline.  ncu showed tensor=30%, issue=26% -> latency/
// barrier-bound, not MMA-bound.  Each wn-pair of warps (threads 64wn..64wn+63)
// loads its OWN 64 B-rows per step and syncs via named bar.sync(1+wn, 64);
// block-wide __syncthreads eliminated from the mainloop (pairs decoupled).
// Warp-parallel shuffle-only routing epilogue.
// ---------------------------------------------------------------------------

__device__ __half g_xh[16 * 32 * 32 * 8 * 16];   // x as fp16
__device__ __half g_ws[27 * 256 * 16];           // W [k][n][16k] fp16, taps>=25 zero

#define HALO_BYTES 23040           // 8q * 5hh * 12ww * 48B
#define OFF_STAGE  23040
#define ST_BYTES   36864           // B: 3 taps x 256 x 48B
#define SMEM_ALLOC 96768           // halo + 2 B stages; dump (66.6KB) reuses [0,..)
#define DPITCH     260             // dump row pitch in floats (1040B, 16-aligned)

__device__ __forceinline__ uint32_t smem_u32(const void* p) {
    uint32_t a;
    asm("{ .reg .u64 t; cvta.to.shared.u64 t, %1; cvt.u32.u64 %0, t; }" : "=r"(a) : "l"(p));
    return a;
}
__device__ __forceinline__ void cp16z(uint32_t dst, const void* src, bool valid) {
    int sz = valid ? 16 : 0;
    asm volatile("cp.async.cg.shared.global [%0], [%1], 16, %2;\n"
                 :: "r"(dst), "l"(src), "r"(sz));
}
__device__ __forceinline__ void cp16(uint32_t dst, const void* src) {
    asm volatile("cp.async.cg.shared.global [%0], [%1], 16;\n" :: "r"(dst), "l"(src));
}
#define CP_COMMIT() asm volatile("cp.async.commit_group;\n")
#define CP_WAIT(n)  asm volatile("cp.async.wait_group %0;\n" :: "n"(n))
#define BAR_PAIR(id) asm volatile("bar.sync %0, 64;" :: "r"(id) : "memory")

#define LDSM4(r, addr) \
    asm volatile("ldmatrix.sync.aligned.m8n8.x4.shared.b16 {%0,%1,%2,%3}, [%4];" \
                 : "=r"((r)[0]), "=r"((r)[1]), "=r"((r)[2]), "=r"((r)[3]) : "r"(addr))

#define MMA16816(c, a, bb0, bb1) \
    asm volatile("mma.sync.aligned.m16n8k16.row.col.f32.f16.f16.f32 " \
                 "{%0,%1,%2,%3}, {%4,%5,%6,%7}, {%8,%9}, {%0,%1,%2,%3};" \
                 : "+f"((c)[0]), "+f"((c)[1]), "+f"((c)[2]), "+f"((c)[3]) \
                 : "r"((a)[0]), "r"((a)[1]), "r"((a)[2]), "r"((a)[3]), \
                   "r"(bb0), "r"(bb1))

// ---------------- merged prep kernel ----------------
__global__ void prep_kernel(const float* __restrict__ x, const float* __restrict__ W) {
    if (blockIdx.x < 2048) {                 // x -> fp16, 4 floats per thread
        int idx = blockIdx.x * 256 + threadIdx.x;
        float4 f = ((const float4*)x)[idx];
        __half h0[4];
        h0[0] = __float2half_rn(f.x);
        h0[1] = __float2half_rn(f.y);
        h0[2] = __float2half_rn(f.z);
        h0[3] = __float2half_rn(f.w);
        *(uint2*)&g_xh[idx * 4] = *(uint2*)h0;
    } else {                                 // W -> [k][n][16] fp16
        int idx = (blockIdx.x - 2048) * 256 + threadIdx.x;   // k*256+co
        if (idx >= 27 * 256) return;
        int co = idx & 255, k = idx >> 8;
#pragma unroll
        for (int cin = 0; cin < 16; ++cin)
            g_ws[idx * 16 + cin] = (k < 25)
                ? __float2half_rn(W[(k * 16 + cin) * 256 + co])
                : __half(0.f);
    }
}

// ---------------- main fused kernel ----------------
// Pair (wn) loads its own 64 n-rows of B for taps 3s..3s+2 (skip taps >= 25).
// 64 threads x 6 cp16 = 384 transfers.
__device__ __forceinline__ void load_B_pair(uint32_t sbase, int s, int stg_i,
                                            int wn, int tp) {
    const uint32_t stg = sbase + OFF_STAGE + stg_i * ST_BYTES;
#pragma unroll
    for (int it = 0; it < 6; ++it) {
        int j = tp + it * 64;                  // 0..383
        int sub = j >> 7, rem = j & 127;
        int half = rem & 1, nl = rem >> 1;     // nl 0..63
        int n = wn * 64 + nl;
        int k2 = 3 * s + sub;
        if (k2 < 25)
            cp16(stg + sub * 12288 + n * 48 + half * 16,
                 &g_ws[((size_t)k2 * 256 + n) * 16 + half * 8]);
    }
}

// Load x halo once: rows (q, hh 0..4, ww 0..11) of 16 halfs at 48B pitch.
__device__ __forceinline__ void load_halo(uint32_t sbase, int h, int w0,
                                          int i_true, int b_base, int t) {
#pragma unroll
    for (int it = 0; it < 4; ++it) {
        int j = t + it * 256;
        if (j < 960) {
            int half = j & 1, row = j >> 1;          // row = q*60 + hh*12 + ww
            int q = row / 60, rem = row - q * 60;
            int hh = rem / 12, ww = rem - hh * 12;
            int hg = h + hh - 2, wg = w0 + ww - 2;
            bool valid = ((unsigned)hg < 32u) && ((unsigned)wg < 32u);
            const __half* src = valid
                ? &g_xh[((((size_t)(b_base + q) * 32 + hg) * 32 + wg) * 8 + i_true) * 16 + half * 8]
                : &g_xh[0];
            cp16z(sbase + q * 2880 + hh * 576 + ww * 48 + half * 16, src, valid);
        }
    }
}

__global__ __launch_bounds__(256, 2) void caps_fused_kernel(
    const float* __restrict__ bias, float* __restrict__ out) {
    extern __shared__ __align__(1024) char sm[];
    const uint32_t sbase = smem_u32(sm);

    const int t = threadIdx.x;
    const int wid = t >> 5, lane = t & 31;
    const int bid = blockIdx.x;
    const int wblk = bid & 3, h = (bid >> 2) & 31, p = bid >> 7;
    const int w0 = wblk * 8;
    const int i_true = p >> 1, b_base = (p & 1) * 8;

    const int wm = wid & 1;        // m block (32 rows each)
    const int wn = wid >> 1;       // n block (64 cols each); pair id
    const int tp = t & 63;         // thread index within pair

    // A ldmatrix per-lane halo address base.
    uint32_t a_base[2];
#pragma unroll
    for (int mi = 0; mi < 2; ++mi) {
        int m = wm * 32 + mi * 16 + (lane & 15);
        int q = m >> 3, wl = m & 7;
        a_base[mi] = sbase + q * 2880 + wl * 48 + (lane >> 4) * 16;
    }
    const uint32_t b_row  = (lane & 7) + ((lane >> 4) << 3);
    const uint32_t b_koff = ((lane >> 3) & 1) * 16;
    const uint32_t b_lane = (wn * 64 + b_row) * 48 + b_koff;

    float acc[2][8][4];
#pragma unroll
    for (int mi = 0; mi < 2; ++mi)
#pragma unroll
        for (int ni = 0; ni < 8; ++ni)
#pragma unroll
            for (int j = 0; j < 4; ++j) acc[mi][ni][j] = 0.f;

    // prologue: halo (all threads) + B stage 0 (pair slice), one group
    load_halo(sbase, h, w0, i_true, b_base, t);
    load_B_pair(sbase, 0, 0, wn, tp);
    CP_COMMIT();
    CP_WAIT(0);
    __syncthreads();                 // halo + all pairs' stage 0 visible

    for (int s = 0; s < 9; ++s) {
        if (s > 0) {
            CP_WAIT(0);              // pair's stage-s slice landed (this thread)
            BAR_PAIR(1 + wn);        // pair-wide: loads visible, compute(s-1) done
        }
        if (s < 8) {                 // prefetch s+1 into buffer of s-1 (pair-freed)
            load_B_pair(sbase, s + 1, (s + 1) & 1, wn, tp);
            CP_COMMIT();
        }

        const uint32_t stg = sbase + OFF_STAGE + (s & 1) * ST_BYTES;
        const int nsub = (s == 8) ? 1 : 3;     // taps 25,26 are zero: skip
        for (int sub = 0; sub < nsub; ++sub) {
            const int k2 = 3 * s + sub;
            const int kh = k2 / 5, kw = k2 - kh * 5;
            const uint32_t a_off = kh * 576 + kw * 48;
            const uint32_t Bb = stg + sub * 12288 + b_lane;
            uint32_t Af[2][4], Bf[4][4];
#pragma unroll
            for (int mi = 0; mi < 2; ++mi) LDSM4(Af[mi], a_base[mi] + a_off);
#pragma unroll
            for (int nt = 0; nt < 4; ++nt) LDSM4(Bf[nt], Bb + nt * 768);
#pragma unroll
            for (int mi = 0; mi < 2; ++mi)
#pragma unroll
                for (int nt = 0; nt < 4; ++nt) {
                    MMA16816(acc[mi][2 * nt],     Af[mi], Bf[nt][0], Bf[nt][1]);
                    MMA16816(acc[mi][2 * nt + 1], Af[mi], Bf[nt][2], Bf[nt][3]);
                }
        }
    }
    __syncthreads();   // all pairs done; halo+stage smem dead -> vote dump

    // ---- dump accumulators: Dsm[row 64][col 256], pitch DPITCH floats ----
    float* Dsm = (float*)sm;
    {
        const int g = lane >> 2, tq = lane & 3;
#pragma unroll
        for (int mi = 0; mi < 2; ++mi)
#pragma unroll
            for (int ni = 0; ni < 8; ++ni) {
                int row = wm * 32 + mi * 16 + g;
                int col = wn * 64 + ni * 8 + tq * 2;
                *(float2*)&Dsm[(size_t)row * DPITCH + col] =
                    make_float2(acc[mi][ni][0], acc[mi][ni][1]);
                *(float2*)&Dsm[(size_t)(row + 8) * DPITCH + col] =
                    make_float2(acc[mi][ni][2], acc[mi][ni][3]);
            }
    }
    __syncthreads();

    // ---- warp-parallel routing: warp wid handles point pt = wid ----
    {
        const int o = lane >> 1, dg = lane & 1;

        float vqv[8][8];
#pragma unroll
        for (int q = 0; q < 8; ++q) {
            const float* rowp = &Dsm[(size_t)(q * 8 + wid) * DPITCH + lane * 8];
            float4 v0 = *(const float4*)rowp;
            float4 v1 = *(const float4*)(rowp + 4);
            vqv[q][0] = v0.x; vqv[q][1] = v0.y; vqv[q][2] = v0.z; vqv[q][3] = v0.w;
            vqv[q][4] = v1.x; vqv[q][5] = v1.y; vqv[q][6] = v1.z; vqv[q][7] = v1.w;
        }
        float bv[8];
        {
            const float4* bp = (const float4*)(bias + o * 16 + dg * 8);
            float4 b0 = bp[0], b1 = bp[1];
            bv[0] = b0.x; bv[1] = b0.y; bv[2] = b0.z; bv[3] = b0.w;
            bv[4] = b1.x; bv[5] = b1.y; bv[6] = b1.z; bv[7] = b1.w;
        }

        float pre[8], act[8], lgv[8];

        // ---- iter 0: route = 1/16 ----
#pragma unroll
        for (int j = 0; j < 8; ++j) {
            float s = bv[j];
#pragma unroll
            for (int q = 0; q < 8; ++q) s = fmaf(0.0625f, vqv[q][j], s);
            pre[j] = s;
        }
        float sq = 0.f;
#pragma unroll
        for (int j = 0; j < 8; ++j) sq = fmaf(pre[j], pre[j], sq);
        sq += __shfl_xor_sync(0xffffffffu, sq, 1);
        float scl = sqrtf(sq) / (1.f + sq);
#pragma unroll
        for (int j = 0; j < 8; ++j) act[j] = pre[j] * scl;

        // agreement -> logits
#pragma unroll
        for (int q = 0; q < 8; ++q) {
            float s = 0.f;
#pragma unroll
            for (int j = 0; j < 8; ++j) s = fmaf(vqv[q][j], act[j], s);
            lgv[q] = s + __shfl_xor_sync(0xffffffffu, s, 1);
        }

#pragma unroll
        for (int it = 1; it < 3; ++it) {
            float mx[8], ex[8], sum[8];
#pragma unroll
            for (int q = 0; q < 8; ++q) mx[q] = lgv[q];
#pragma unroll
            for (int st = 2; st <= 16; st <<= 1)
#pragma unroll
                for (int q = 0; q < 8; ++q)
                    mx[q] = fmaxf(mx[q], __shfl_xor_sync(0xffffffffu, mx[q], st));
#pragma unroll
            for (int q = 0; q < 8; ++q) { ex[q] = __expf(lgv[q] - mx[q]); sum[q] = ex[q]; }
#pragma unroll
            for (int st = 2; st <= 16; st <<= 1)
#pragma unroll
                for (int q = 0; q < 8; ++q)
                    sum[q] += __shfl_xor_sync(0xffffffffu, sum[q], st);
            float route[8];
#pragma unroll
            for (int q = 0; q < 8; ++q) route[q] = ex[q] / sum[q];

#pragma unroll
            for (int j = 0; j < 8; ++j) {
                float s = bv[j];
#pragma unroll
                for (int q = 0; q < 8; ++q) s = fmaf(route[q], vqv[q][j], s);
                pre[j] = s;
            }
            sq = 0.f;
#pragma unroll
            for (int j = 0; j < 8; ++j) sq = fmaf(pre[j], pre[j], sq);
            sq += __shfl_xor_sync(0xffffffffu, sq, 1);
            scl = sqrtf(sq) / (1.f + sq);
#pragma unroll
            for (int j = 0; j < 8; ++j) act[j] = pre[j] * scl;

            if (it == 1) {
#pragma unroll
                for (int q = 0; q < 8; ++q) {
                    float s = 0.f;
#pragma unroll
                    for (int j = 0; j < 8; ++j) s = fmaf(vqv[q][j], act[j], s);
                    lgv[q] += s + __shfl_xor_sync(0xffffffffu, s, 1);
                }
            }
        }

        float* op = out + (((size_t)p * 32 + h) * 32 + (w0 + wid)) * 256 + lane * 8;
        *(float4*)op       = make_float4(act[0], act[1], act[2], act[3]);
        *(float4*)(op + 4) = make_float4(act[4], act[5], act[6], act[7]);
    }
}

extern "C" void kernel_launch(void* const* d_in, const int* in_sizes, int n_in,
                              void* d_out, int out_size) {
    const float* x  = (const float*)d_in[0];
    const float* Wt = (const float*)d_in[1];
    const float* b  = (const float*)d_in[2];
    float* out = (float*)d_out;

    cudaFuncSetAttribute(caps_fused_kernel,
                         cudaFuncAttributeMaxDynamicSharedMemorySize, SMEM_ALLOC);

    prep_kernel<<<2048 + 27, 256>>>(x, Wt);
    caps_fused_kernel<<<2048, 256, SMEM_ALLOC>>>(b, out);
}